// round 1
// baseline (speedup 1.0000x reference)
#include <cuda_runtime.h>
#include <math.h>

#define BB 8
#define NN 20000
#define EE 40000
#define HH 128
#define TT 64
#define LL 4

// ---------------- scratch (static device globals; no runtime alloc) -------
__device__ float g_temb[BB * HH];
__device__ float g_table4[4 * HH];
__device__ float g_counts[NN];
__device__ float g_h[BB * NN * HH];        //  82 MB
__device__ float g_agg[BB * NN * HH];      //  82 MB
__device__ float g_x[BB * NN * 3];
__device__ float g_cupd[BB * NN * 3];
__device__ float g_dist[BB * EE];
__device__ float g_cdn[BB * EE * 3];
__device__ float g_m1[BB * EE * HH];       // 164 MB
__device__ float g_m[BB * EE * HH];        // 164 MB
__device__ float g_c1[BB * EE * HH];       // 164 MB
__device__ float g_cw[BB * EE];
__device__ float g_n1[BB * NN * HH];       //  82 MB (also reused for o1)

__device__ __forceinline__ float silu_f(float v) {
    return v / (1.f + __expf(-v));
}

// ---------------- generic tiled SGEMM, N fixed at 128 ---------------------
// AMODE: 0 = direct A[M,K]
//        1 = edge gather: row=(b,e); k<128 -> h[b,src[e],k]; k<256 -> h[b,dst[e],k-128]; k==256 -> dist
//        2 = concat: k<128 -> hbuf[row,k]; else h2buf[row,k-128]
// EPI:   0 = silu(acc + bias)
//        1 = Cres + acc + bias
template <int AMODE, int EPI>
__launch_bounds__(256)
__global__ void gemm_k(const float* __restrict__ A,
                       const float* __restrict__ W,
                       const float* __restrict__ bias,
                       const float* __restrict__ Cres,
                       float* __restrict__ out,
                       int K, int rowsPerB,
                       const float* __restrict__ hbuf,
                       const float* __restrict__ h2buf,
                       const int* __restrict__ bonds,
                       const float* __restrict__ distv)
{
    __shared__ float As[8][64];
    __shared__ float Bs[8][128];
    const int tid  = threadIdx.x;
    const int row0 = blockIdx.x * 64;

    // A-loader mapping: 4 threads per row, 2 consecutive k each
    const int lm   = tid >> 2;          // 0..63 (row within tile)
    const int lk   = (tid & 3) * 2;     // 0,2,4,6
    const int arow = row0 + lm;

    const float* aptr0 = nullptr;
    const float* aptr1 = nullptr;
    float dval = 0.f;
    if (AMODE == 0) {
        aptr0 = A + (long)arow * K;
    } else if (AMODE == 1) {
        int b = arow / rowsPerB;
        int e = arow - b * rowsPerB;
        int s = bonds[2 * e], d = bonds[2 * e + 1];
        aptr0 = hbuf + ((long)b * NN + s) * HH;
        aptr1 = hbuf + ((long)b * NN + d) * HH;
        dval  = distv[arow];
    } else {
        aptr0 = hbuf  + (long)arow * HH;
        aptr1 = h2buf + (long)arow * HH;
    }

    // B-loader mapping
    const int bk = tid >> 5;            // 0..7
    const int bc = (tid & 31) * 4;

    const int tx = tid & 15;            // N dir (8 cols each)
    const int ty = tid >> 4;            // M dir (4 rows each)

    float acc[4][8];
#pragma unroll
    for (int i = 0; i < 4; i++)
#pragma unroll
        for (int j = 0; j < 8; j++) acc[i][j] = 0.f;

    for (int k0 = 0; k0 < K; k0 += 8) {
#pragma unroll
        for (int i = 0; i < 2; i++) {
            int gk = k0 + lk + i;
            float v = 0.f;
            if (gk < K) {
                if (AMODE == 0) v = aptr0[gk];
                else if (AMODE == 1)
                    v = (gk < 128) ? aptr0[gk] : (gk < 256 ? aptr1[gk - 128] : dval);
                else
                    v = (gk < 128) ? aptr0[gk] : aptr1[gk - 128];
            }
            As[lk + i][lm] = v;
        }
        {
            int gk = k0 + bk;
            float4 v = make_float4(0.f, 0.f, 0.f, 0.f);
            if (gk < K) v = *reinterpret_cast<const float4*>(W + (long)gk * 128 + bc);
            *reinterpret_cast<float4*>(&Bs[bk][bc]) = v;
        }
        __syncthreads();
#pragma unroll
        for (int kk = 0; kk < 8; kk++) {
            float a0[4], b0[8];
#pragma unroll
            for (int i = 0; i < 4; i++) a0[i] = As[kk][ty * 4 + i];
#pragma unroll
            for (int j = 0; j < 8; j++) b0[j] = Bs[kk][tx * 8 + j];
#pragma unroll
            for (int i = 0; i < 4; i++)
#pragma unroll
                for (int j = 0; j < 8; j++) acc[i][j] = fmaf(a0[i], b0[j], acc[i][j]);
        }
        __syncthreads();
    }

#pragma unroll
    for (int i = 0; i < 4; i++) {
        int row = row0 + ty * 4 + i;
#pragma unroll
        for (int j = 0; j < 8; j++) {
            int col = tx * 8 + j;
            float v = acc[i][j] + bias[col];
            if (EPI == 0) v = silu_f(v);
            else          v += Cres[(long)row * 128 + col];
            out[(long)row * 128 + col] = v;
        }
    }
}

// ---------------- small kernels -------------------------------------------
__global__ void time_embed_k(const float* __restrict__ t,
                             const float* __restrict__ W1, const float* __restrict__ b1,
                             const float* __restrict__ W2, const float* __restrict__ b2)
{
    __shared__ float te[BB][TT];
    __shared__ float s1[BB][HH];
    int tid = threadIdx.x;  // 128
    const int half = TT / 2;
    for (int idx = tid; idx < BB * TT; idx += 128) {
        int b = idx / TT, k = idx % TT;
        int kk = (k < half) ? k : (k - half);
        float f = __expf((float)kk * (-logf(10000.f) / (float)(half - 1)));
        float a = t[b] * f;
        te[b][k] = (k < half) ? sinf(a) : cosf(a);
    }
    __syncthreads();
    for (int b = 0; b < BB; b++) {
        float acc = b1[tid];
        for (int k = 0; k < TT; k++) acc += te[b][k] * W1[k * HH + tid];
        s1[b][tid] = silu_f(acc);
    }
    __syncthreads();
    for (int b = 0; b < BB; b++) {
        float acc = b2[tid];
        for (int k = 0; k < HH; k++) acc += s1[b][k] * W2[k * HH + tid];
        g_temb[b * HH + tid] = acc;
    }
}

__global__ void table4_k(const float* __restrict__ emb,
                         const float* __restrict__ Wn, const float* __restrict__ bn)
{
    int a = blockIdx.x;       // 4 blocks
    int j = threadIdx.x;      // 128
    float acc = bn[j];
    for (int k = 0; k < HH; k++) acc += emb[a * HH + k] * Wn[k * HH + j];
    g_table4[a * HH + j] = acc;
}

__global__ void h_init_k(const int* __restrict__ types)
{
    long idx = (long)blockIdx.x * 256 + threadIdx.x;
    if (idx >= (long)BB * NN * HH) return;
    int j  = (int)(idx & 127);
    long bn = idx >> 7;
    int n = (int)(bn % NN);
    int b = (int)(bn / NN);
    g_h[idx] = g_table4[types[n] * HH + j] + g_temb[b * HH + j];
}

__global__ void init_x_k(const float* __restrict__ x)
{
    int idx = blockIdx.x * 256 + threadIdx.x;
    if (idx < BB * NN * 3) g_x[idx] = x[idx];
}

__global__ void zero_k(float* __restrict__ p, long n)
{
    long idx = (long)blockIdx.x * 256 + threadIdx.x;
    if (idx < n) p[idx] = 0.f;
}

__global__ void counts_k(const int* __restrict__ bonds)
{
    int e = blockIdx.x * 256 + threadIdx.x;
    if (e >= EE) return;
    atomicAdd(&g_counts[bonds[2 * e + 1]], 1.f);
    atomicAdd(&g_counts[bonds[2 * e]], 1.f);
}

__global__ void edge_geom_k(const int* __restrict__ bonds)
{
    int idx = blockIdx.x * 256 + threadIdx.x;
    if (idx >= BB * EE) return;
    int b = idx / EE, e = idx - b * EE;
    int s = bonds[2 * e], d = bonds[2 * e + 1];
    const float* xs = g_x + ((long)b * NN + s) * 3;
    const float* xd = g_x + ((long)b * NN + d) * 3;
    float dx = xd[0] - xs[0], dy = xd[1] - xs[1], dz = xd[2] - xs[2];
    float dist = sqrtf(dx * dx + dy * dy + dz * dz);
    g_dist[idx] = dist;
    float inv = 1.f / (dist + 1e-8f);
    g_cdn[idx * 3 + 0] = dx * inv;
    g_cdn[idx * 3 + 1] = dy * inv;
    g_cdn[idx * 3 + 2] = dz * inv;
}

__global__ void cw_k(const float* __restrict__ Wc2)
{
    int warp = (blockIdx.x * 256 + threadIdx.x) >> 5;
    int lane = threadIdx.x & 31;
    if (warp >= BB * EE) return;
    const float* c1 = g_c1 + (long)warp * HH;
    float acc = 0.f;
#pragma unroll
    for (int i = 0; i < 4; i++) {
        int j = lane + i * 32;
        acc += c1[j] * Wc2[j];
    }
#pragma unroll
    for (int o = 16; o; o >>= 1) acc += __shfl_xor_sync(0xffffffffu, acc, o);
    if (lane == 0) g_cw[warp] = acc;
}

__global__ void agg_scatter_k(const int* __restrict__ bonds)
{
    long idx = (long)blockIdx.x * 256 + threadIdx.x;
    if (idx >= (long)BB * EE * HH) return;
    int j  = (int)(idx & 127);
    long be = idx >> 7;
    int b = (int)(be / EE), e = (int)(be - (long)b * EE);
    float v = g_m[idx];
    int s = bonds[2 * e], d = bonds[2 * e + 1];
    atomicAdd(&g_agg[((long)b * NN + d) * HH + j], v);
    atomicAdd(&g_agg[((long)b * NN + s) * HH + j], v);
}

__global__ void coord_scatter_k(const int* __restrict__ bonds)
{
    int idx = blockIdx.x * 256 + threadIdx.x;
    if (idx >= BB * EE) return;
    int b = idx / EE, e = idx - b * EE;
    int s = bonds[2 * e], d = bonds[2 * e + 1];
    float w = g_cw[idx];
#pragma unroll
    for (int c = 0; c < 3; c++) {
        float u = g_cdn[idx * 3 + c] * w;
        atomicAdd(&g_cupd[((long)b * NN + d) * 3 + c], u);
        atomicAdd(&g_cupd[((long)b * NN + s) * 3 + c], -u);
    }
}

__global__ void x_update_k()
{
    int idx = blockIdx.x * 256 + threadIdx.x;
    if (idx >= BB * NN * 3) return;
    int n = (idx / 3) % NN;
    g_x[idx] += g_cupd[idx] / fmaxf(g_counts[n], 1.f);
}

__global__ void out_k(const float* __restrict__ Wo2, const float* __restrict__ bo2,
                      const float* __restrict__ x_in, float* __restrict__ out)
{
    int warp = (blockIdx.x * 256 + threadIdx.x) >> 5;
    int lane = threadIdx.x & 31;
    if (warp >= BB * NN) return;
    const float* o1 = g_n1 + (long)warp * HH;
    float a0 = 0.f, a1 = 0.f, a2 = 0.f;
#pragma unroll
    for (int i = 0; i < 4; i++) {
        int j = lane + i * 32;
        float v = o1[j];
        a0 += v * Wo2[j * 3 + 0];
        a1 += v * Wo2[j * 3 + 1];
        a2 += v * Wo2[j * 3 + 2];
    }
#pragma unroll
    for (int o = 16; o; o >>= 1) {
        a0 += __shfl_xor_sync(0xffffffffu, a0, o);
        a1 += __shfl_xor_sync(0xffffffffu, a1, o);
        a2 += __shfl_xor_sync(0xffffffffu, a2, o);
    }
    if (lane == 0) {
        int base = warp * 3;
        out[base + 0] = a0 + bo2[0] + g_x[base + 0] - x_in[base + 0];
        out[base + 1] = a1 + bo2[1] + g_x[base + 1] - x_in[base + 1];
        out[base + 2] = a2 + bo2[2] + g_x[base + 2] - x_in[base + 2];
    }
}

// ---------------- launch ---------------------------------------------------
static inline int cdiv(long n, int b) { return (int)((n + b - 1) / b); }

extern "C" void kernel_launch(void* const* d_in, const int* in_sizes, int n_in,
                              void* d_out, int out_size)
{
    const float* x      = (const float*)d_in[0];
    const float* t      = (const float*)d_in[1];
    const int*   types  = (const int*)d_in[2];
    const int*   bonds  = (const int*)d_in[3];
    const float* emb    = (const float*)d_in[4];
    const float* W_t1   = (const float*)d_in[5];
    const float* b_t1   = (const float*)d_in[6];
    const float* W_t2   = (const float*)d_in[7];
    const float* b_t2   = (const float*)d_in[8];
    const float* W_node = (const float*)d_in[9];
    const float* b_node = (const float*)d_in[10];
    const float* Wm1    = (const float*)d_in[11];
    const float* bm1    = (const float*)d_in[12];
    const float* Wm2    = (const float*)d_in[13];
    const float* bm2    = (const float*)d_in[14];
    const float* Wn1    = (const float*)d_in[15];
    const float* bn1    = (const float*)d_in[16];
    const float* Wn2    = (const float*)d_in[17];
    const float* bn2    = (const float*)d_in[18];
    const float* Wc1    = (const float*)d_in[19];
    const float* bc1    = (const float*)d_in[20];
    const float* Wc2    = (const float*)d_in[21];
    const float* Wo1    = (const float*)d_in[22];
    const float* bo1    = (const float*)d_in[23];
    const float* Wo2    = (const float*)d_in[24];
    const float* bo2    = (const float*)d_in[25];
    float* out = (float*)d_out;

    float *p_h, *p_agg, *p_m1, *p_m, *p_c1, *p_n1, *p_counts, *p_cupd, *p_dist;
    cudaGetSymbolAddress((void**)&p_h, g_h);
    cudaGetSymbolAddress((void**)&p_agg, g_agg);
    cudaGetSymbolAddress((void**)&p_m1, g_m1);
    cudaGetSymbolAddress((void**)&p_m, g_m);
    cudaGetSymbolAddress((void**)&p_c1, g_c1);
    cudaGetSymbolAddress((void**)&p_n1, g_n1);
    cudaGetSymbolAddress((void**)&p_counts, g_counts);
    cudaGetSymbolAddress((void**)&p_cupd, g_cupd);
    cudaGetSymbolAddress((void**)&p_dist, g_dist);

    time_embed_k<<<1, 128>>>(t, W_t1, b_t1, W_t2, b_t2);
    table4_k<<<4, 128>>>(emb, W_node, b_node);
    h_init_k<<<cdiv((long)BB * NN * HH, 256), 256>>>(types);
    init_x_k<<<cdiv((long)BB * NN * 3, 256), 256>>>(x);
    zero_k<<<cdiv(NN, 256), 256>>>(p_counts, NN);
    counts_k<<<cdiv(EE, 256), 256>>>(bonds);

    const int gridE = BB * EE / 64;  // 5000
    const int gridN = BB * NN / 64;  // 2500

    for (int l = 0; l < LL; l++) {
        zero_k<<<cdiv((long)BB * NN * HH, 256), 256>>>(p_agg, (long)BB * NN * HH);
        zero_k<<<cdiv((long)BB * NN * 3, 256), 256>>>(p_cupd, (long)BB * NN * 3);
        edge_geom_k<<<cdiv((long)BB * EE, 256), 256>>>(bonds);

        // m1 = silu(msg_in @ Wm1 + bm1), msg_in gathered on the fly (K=257)
        gemm_k<1, 0><<<gridE, 256>>>(nullptr, Wm1 + (long)l * 257 * HH, bm1 + l * HH,
                                     nullptr, p_m1, 257, EE, p_h, nullptr, bonds, p_dist);
        // m = silu(m1 @ Wm2 + bm2)
        gemm_k<0, 0><<<gridE, 256>>>(p_m1, Wm2 + (long)l * HH * HH, bm2 + l * HH,
                                     nullptr, p_m, 128, 0, nullptr, nullptr, nullptr, nullptr);
        // c1 = silu(m @ Wc1 + bc1)
        gemm_k<0, 0><<<gridE, 256>>>(p_m, Wc1 + (long)l * HH * HH, bc1 + l * HH,
                                     nullptr, p_c1, 128, 0, nullptr, nullptr, nullptr, nullptr);
        cw_k<<<cdiv((long)BB * EE * 32, 256), 256>>>(Wc2 + l * HH);

        agg_scatter_k<<<cdiv((long)BB * EE * HH, 256), 256>>>(bonds);
        coord_scatter_k<<<cdiv((long)BB * EE, 256), 256>>>(bonds);

        // n1 = silu([h, agg] @ Wn1 + bn1)  (K=256)
        gemm_k<2, 0><<<gridN, 256>>>(nullptr, Wn1 + (long)l * 256 * HH, bn1 + l * HH,
                                     nullptr, p_n1, 256, NN, p_h, p_agg, nullptr, nullptr);
        // h = h + n1 @ Wn2 + bn2 (in-place residual)
        gemm_k<0, 1><<<gridN, 256>>>(p_n1, Wn2 + (long)l * HH * HH, bn2 + l * HH,
                                     p_h, p_h, 128, 0, nullptr, nullptr, nullptr, nullptr);

        x_update_k<<<cdiv((long)BB * NN * 3, 256), 256>>>();
    }

    // o1 = silu(h @ W_o1 + b_o1)  (reuse g_n1)
    gemm_k<0, 0><<<gridN, 256>>>(p_h, Wo1, bo1,
                                 nullptr, p_n1, 128, 0, nullptr, nullptr, nullptr, nullptr);
    out_k<<<cdiv((long)BB * NN * 32, 256), 256>>>(Wo2, bo2, x, out);
}

// round 3
// speedup vs baseline: 2.0075x; 2.0075x over previous
#include <cuda_runtime.h>
#include <mma.h>
#include <math.h>
#include <stdint.h>

using namespace nvcuda;

#define BB 8
#define NN 20000
#define EE 40000
#define HH 128
#define TT 64
#define LL 4

__device__ __forceinline__ uint32_t f2tf(float f) {
    uint32_t u;
    asm("cvt.rna.tf32.f32 %0, %1;" : "=r"(u) : "f"(f));
    return u;
}
__device__ __forceinline__ float silu_f(float v) { return v / (1.f + __expf(-v)); }

// ---------------- scratch (static device globals) --------------------------
__device__ float g_temb[BB * HH];
__device__ float g_table4[4 * HH];
__device__ float g_h[BB * NN * HH];
__device__ float g_agg[BB * NN * HH];
__device__ float g_x[BB * NN * 3];
__device__ float g_cupd[BB * NN * 3];
__device__ float g_dist[BB * EE];
__device__ float g_cdn[BB * EE * 3];
__device__ float g_m1[BB * EE * HH];
__device__ float g_m[BB * EE * HH];
__device__ float g_n1[BB * NN * HH];
__device__ int   g_deg[NN];
__device__ int   g_off[NN + 1];
__device__ int   g_cur[NN];
__device__ int   g_csr[2 * EE];

// ---------------- wmma tf32 GEMM, tile 128x128, N fixed 128 ----------------
// AMODE: 0 direct A[M,K]; 1 edge gather (k<128: h[src], else h[dst]); 2 concat (h|agg)
// EPI:   0 silu(acc + bias [+ dist*extra]) -> out
//        1 acc + bias + Cres               -> out
//        2 silu(acc + bias) . extra -> cw; coord atomics (no out)
#define LDA 36
#define LDB 136
#define LDC 136
#define DSMEM_BYTES (128 * LDC * 4)   // 69632; As/Bs alias the front of it

template <int AMODE, int EPI>
__global__ void __launch_bounds__(256)
gemm_tc(const float* __restrict__ A, const float* __restrict__ W,
        const float* __restrict__ bias, const float* __restrict__ extra,
        const float* __restrict__ Cres, float* __restrict__ out,
        int K, const int* __restrict__ bonds)
{
    extern __shared__ float dyn[];
    float* As = dyn;                       // [128][LDA]
    float* Bs = dyn + 128 * LDA;           // [32][LDB]
    float* Cs = dyn;                       // [128][LDC] (aliases As/Bs, used after)

    __shared__ float bias_s[128];
    __shared__ float extra_s[128];
    __shared__ const float* pA0[128];
    __shared__ const float* pA1[128];

    const int tid  = threadIdx.x;
    const int wid  = tid >> 5;
    const long row0 = (long)blockIdx.x * 128;

    if (tid < 128) {
        bias_s[tid] = bias[tid];
        if (AMODE == 1 || EPI == 2) extra_s[tid] = extra[tid];
        if (AMODE == 1) {
            long gr = row0 + tid;
            int b = (int)(gr / EE), e = (int)(gr - (long)b * EE);
            int s = bonds[2 * e], d = bonds[2 * e + 1];
            pA0[tid] = g_h + ((long)b * NN + s) * HH;
            pA1[tid] = g_h + ((long)b * NN + d) * HH;
        }
    }
    __syncthreads();

    const int wm = wid & 3;        // M quadrant (32 rows)
    const int wn = wid >> 2;       // N half (64 cols)

    wmma::fragment<wmma::accumulator, 16, 16, 8, float> c[2][4];
#pragma unroll
    for (int i = 0; i < 2; i++)
#pragma unroll
        for (int j = 0; j < 4; j++) wmma::fill_fragment(c[i][j], 0.f);

    // A-loader: each thread 16 floats of one row; B-loader: 16 floats of one k-row
    const int arow  = tid >> 1;
    const int akb   = (tid & 1) * 16;
    const int bkrow = tid >> 3;
    const int bnc   = (tid & 7) * 16;

    for (int k0 = 0; k0 < K; k0 += 32) {
        // ---- A tile (gather + tf32 round) ----
        const float* abase;
        if (AMODE == 0) {
            abase = A + (row0 + arow) * (long)K + k0 + akb;
        } else if (AMODE == 1) {
            abase = ((k0 < 128) ? pA0[arow] : pA1[arow]) + (k0 & 127) + akb;
        } else {
            long gr = row0 + arow;
            abase = ((k0 < 128) ? (g_h + gr * HH) : (g_agg + gr * HH)) + (k0 & 127) + akb;
        }
#pragma unroll
        for (int q = 0; q < 4; q++) {
            float4 v = *(const float4*)(abase + q * 4);
            uint4 av;
            av.x = f2tf(v.x); av.y = f2tf(v.y); av.z = f2tf(v.z); av.w = f2tf(v.w);
            *(uint4*)(As + arow * LDA + akb + q * 4) = av;
        }
        // ---- B tile (original K-major weights, tf32 round) ----
        const float* wbase = W + (long)(k0 + bkrow) * 128 + bnc;
#pragma unroll
        for (int q = 0; q < 4; q++) {
            float4 v = *(const float4*)(wbase + q * 4);
            uint4 bv;
            bv.x = f2tf(v.x); bv.y = f2tf(v.y); bv.z = f2tf(v.z); bv.w = f2tf(v.w);
            *(uint4*)(Bs + bkrow * LDB + bnc + q * 4) = bv;
        }
        __syncthreads();

#pragma unroll
        for (int kk = 0; kk < 32; kk += 8) {
            wmma::fragment<wmma::matrix_a, 16, 16, 8, wmma::precision::tf32, wmma::row_major> a[2];
            wmma::fragment<wmma::matrix_b, 16, 16, 8, wmma::precision::tf32, wmma::row_major> b[4];
#pragma unroll
            for (int i = 0; i < 2; i++)
                wmma::load_matrix_sync(a[i], As + (wm * 32 + i * 16) * LDA + kk, LDA);
#pragma unroll
            for (int j = 0; j < 4; j++)
                wmma::load_matrix_sync(b[j], Bs + kk * LDB + wn * 64 + j * 16, LDB);
#pragma unroll
            for (int i = 0; i < 2; i++)
#pragma unroll
                for (int j = 0; j < 4; j++)
                    wmma::mma_sync(c[i][j], a[i], b[j], c[i][j]);
        }
        __syncthreads();
    }

    // ---- stage accumulators to smem ----
#pragma unroll
    for (int i = 0; i < 2; i++)
#pragma unroll
        for (int j = 0; j < 4; j++)
            wmma::store_matrix_sync(Cs + (wm * 32 + i * 16) * LDC + wn * 64 + j * 16,
                                    c[i][j], LDC, wmma::mem_row_major);
    __syncthreads();

    // ---- epilogue ----
    if (EPI == 2) {
        if (tid < 128) {
            long gr = row0 + tid;
            float cw = 0.f;
            const float* crow = Cs + tid * LDC;
#pragma unroll 16
            for (int col = 0; col < 128; col++)
                cw += silu_f(crow[col] + bias_s[col]) * extra_s[col];
            int b = (int)(gr / EE), e = (int)(gr - (long)b * EE);
            int s = bonds[2 * e], d = bonds[2 * e + 1];
            const float* cd = g_cdn + gr * 3;
#pragma unroll
            for (int cc = 0; cc < 3; cc++) {
                float u = cd[cc] * cw;
                atomicAdd(&g_cupd[((long)b * NN + d) * 3 + cc], u);
                atomicAdd(&g_cupd[((long)b * NN + s) * 3 + cc], -u);
            }
        }
    } else {
        const int row = tid >> 1;
        const int cb  = (tid & 1) * 64;
        const long gr = row0 + row;
        float dv = 0.f;
        if (AMODE == 1) dv = g_dist[gr];
        const float* crow = Cs + row * LDC + cb;
#pragma unroll
        for (int j = 0; j < 64; j += 4) {
            float4 v = *(const float4*)(crow + j);
            float vv[4] = {v.x, v.y, v.z, v.w};
            float4 cr;
            if (EPI == 1) cr = *(const float4*)(Cres + gr * HH + cb + j);
#pragma unroll
            for (int q = 0; q < 4; q++) {
                int col = cb + j + q;
                float t = vv[q];
                if (AMODE == 1) t += dv * extra_s[col];
                t += bias_s[col];
                if (EPI == 0) t = silu_f(t);
                vv[q] = t;
            }
            if (EPI == 1) { vv[0] += cr.x; vv[1] += cr.y; vv[2] += cr.z; vv[3] += cr.w; }
            float4 o; o.x = vv[0]; o.y = vv[1]; o.z = vv[2]; o.w = vv[3];
            *(float4*)(out + gr * HH + cb + j) = o;
        }
    }
}

// ---------------- small kernels -------------------------------------------
__global__ void time_embed_k(const float* __restrict__ t,
                             const float* __restrict__ W1, const float* __restrict__ b1,
                             const float* __restrict__ W2, const float* __restrict__ b2)
{
    __shared__ float te[BB][TT];
    __shared__ float s1[BB][HH];
    int tid = threadIdx.x;
    const int half = TT / 2;
    for (int idx = tid; idx < BB * TT; idx += 128) {
        int b = idx / TT, k = idx % TT;
        int kk = (k < half) ? k : (k - half);
        float f = __expf((float)kk * (-logf(10000.f) / (float)(half - 1)));
        float a = t[b] * f;
        te[b][k] = (k < half) ? sinf(a) : cosf(a);
    }
    __syncthreads();
    for (int b = 0; b < BB; b++) {
        float acc = b1[tid];
        for (int k = 0; k < TT; k++) acc += te[b][k] * W1[k * HH + tid];
        s1[b][tid] = silu_f(acc);
    }
    __syncthreads();
    for (int b = 0; b < BB; b++) {
        float acc = b2[tid];
        for (int k = 0; k < HH; k++) acc += s1[b][k] * W2[k * HH + tid];
        g_temb[b * HH + tid] = acc;
    }
}

__global__ void table4_k(const float* __restrict__ emb,
                         const float* __restrict__ Wn, const float* __restrict__ bn)
{
    int a = blockIdx.x, j = threadIdx.x;
    float acc = bn[j];
    for (int k = 0; k < HH; k++) acc += emb[a * HH + k] * Wn[k * HH + j];
    g_table4[a * HH + j] = acc;
}

__global__ void h_init_k(const int* __restrict__ types)
{
    long idx = (long)blockIdx.x * 256 + threadIdx.x;
    if (idx >= (long)BB * NN * HH) return;
    int j = (int)(idx & 127);
    long bn = idx >> 7;
    int n = (int)(bn % NN), b = (int)(bn / NN);
    g_h[idx] = g_table4[types[n] * HH + j] + g_temb[b * HH + j];
}

__global__ void init_x_k(const float* __restrict__ x)
{
    int idx = blockIdx.x * 256 + threadIdx.x;
    if (idx < BB * NN * 3) g_x[idx] = x[idx];
}

__global__ void zero_f_k(float* __restrict__ p, long n)
{
    long idx = (long)blockIdx.x * 256 + threadIdx.x;
    if (idx < n) p[idx] = 0.f;
}
__global__ void zero_i_k(int* __restrict__ p, int n)
{
    int idx = blockIdx.x * 256 + threadIdx.x;
    if (idx < n) p[idx] = 0;
}

__global__ void deg_count_k(const int* __restrict__ bonds)
{
    int e = blockIdx.x * 256 + threadIdx.x;
    if (e >= EE) return;
    atomicAdd(&g_deg[bonds[2 * e]], 1);
    atomicAdd(&g_deg[bonds[2 * e + 1]], 1);
}

__global__ void scan_k()
{
    __shared__ int sh[256];
    __shared__ int base;
    int tid = threadIdx.x;
    if (tid == 0) base = 0;
    __syncthreads();
    for (int i0 = 0; i0 < NN; i0 += 256) {
        int i = i0 + tid;
        int v = (i < NN) ? g_deg[i] : 0;
        sh[tid] = v;
        __syncthreads();
        for (int o = 1; o < 256; o <<= 1) {
            int t = (tid >= o) ? sh[tid - o] : 0;
            __syncthreads();
            sh[tid] += t;
            __syncthreads();
        }
        int excl = base + sh[tid] - v;
        if (i < NN) { g_off[i] = excl; g_cur[i] = excl; }
        __syncthreads();
        if (tid == 255) base += sh[255];
        __syncthreads();
    }
    if (tid == 0) g_off[NN] = base;
}

__global__ void fill_k(const int* __restrict__ bonds)
{
    int e = blockIdx.x * 256 + threadIdx.x;
    if (e >= EE) return;
    int s = bonds[2 * e], d = bonds[2 * e + 1];
    int p = atomicAdd(&g_cur[s], 1); g_csr[p] = e;
    int q = atomicAdd(&g_cur[d], 1); g_csr[q] = e;
}

__global__ void edge_geom_k(const int* __restrict__ bonds)
{
    int idx = blockIdx.x * 256 + threadIdx.x;
    if (idx >= BB * EE) return;
    int b = idx / EE, e = idx - b * EE;
    int s = bonds[2 * e], d = bonds[2 * e + 1];
    const float* xs = g_x + ((long)b * NN + s) * 3;
    const float* xd = g_x + ((long)b * NN + d) * 3;
    float dx = xd[0] - xs[0], dy = xd[1] - xs[1], dz = xd[2] - xs[2];
    float dist = sqrtf(dx * dx + dy * dy + dz * dz);
    g_dist[idx] = dist;
    float inv = 1.f / (dist + 1e-8f);
    g_cdn[idx * 3 + 0] = dx * inv;
    g_cdn[idx * 3 + 1] = dy * inv;
    g_cdn[idx * 3 + 2] = dz * inv;
}

// agg[b,n,:] = sum over incident edges of m[b,e,:] (CSR gather, no atomics)
__global__ void agg_gather_k()
{
    int warp = (blockIdx.x * 256 + threadIdx.x) >> 5;
    int lane = threadIdx.x & 31;
    if (warp >= BB * NN) return;
    int b = warp / NN, n = warp - b * NN;
    int o0 = g_off[n], o1 = g_off[n + 1];
    float4 acc = make_float4(0.f, 0.f, 0.f, 0.f);
    for (int j = o0; j < o1; j++) {
        int e = g_csr[j];
        float4 v = ((const float4*)(g_m + ((long)b * EE + e) * HH))[lane];
        acc.x += v.x; acc.y += v.y; acc.z += v.z; acc.w += v.w;
    }
    ((float4*)(g_agg + (long)warp * HH))[lane] = acc;
}

__global__ void x_update_k()
{
    int idx = blockIdx.x * 256 + threadIdx.x;
    if (idx >= BB * NN * 3) return;
    int n = (idx / 3) % NN;
    g_x[idx] += g_cupd[idx] / fmaxf((float)g_deg[n], 1.f);
}

__global__ void out_k(const float* __restrict__ Wo2, const float* __restrict__ bo2,
                      const float* __restrict__ x_in, float* __restrict__ out)
{
    int warp = (blockIdx.x * 256 + threadIdx.x) >> 5;
    int lane = threadIdx.x & 31;
    if (warp >= BB * NN) return;
    const float* o1 = g_n1 + (long)warp * HH;
    float a0 = 0.f, a1 = 0.f, a2 = 0.f;
#pragma unroll
    for (int i = 0; i < 4; i++) {
        int j = lane + i * 32;
        float v = o1[j];
        a0 += v * Wo2[j * 3 + 0];
        a1 += v * Wo2[j * 3 + 1];
        a2 += v * Wo2[j * 3 + 2];
    }
#pragma unroll
    for (int o = 16; o; o >>= 1) {
        a0 += __shfl_xor_sync(0xffffffffu, a0, o);
        a1 += __shfl_xor_sync(0xffffffffu, a1, o);
        a2 += __shfl_xor_sync(0xffffffffu, a2, o);
    }
    if (lane == 0) {
        int base = warp * 3;
        out[base + 0] = a0 + bo2[0] + g_x[base + 0] - x_in[base + 0];
        out[base + 1] = a1 + bo2[1] + g_x[base + 1] - x_in[base + 1];
        out[base + 2] = a2 + bo2[2] + g_x[base + 2] - x_in[base + 2];
    }
}

// ---------------- launch ---------------------------------------------------
static inline int cdiv(long n, int b) { return (int)((n + b - 1) / b); }

extern "C" void kernel_launch(void* const* d_in, const int* in_sizes, int n_in,
                              void* d_out, int out_size)
{
    const float* x      = (const float*)d_in[0];
    const float* t      = (const float*)d_in[1];
    const int*   types  = (const int*)d_in[2];
    const int*   bonds  = (const int*)d_in[3];
    const float* emb    = (const float*)d_in[4];
    const float* W_t1   = (const float*)d_in[5];
    const float* b_t1   = (const float*)d_in[6];
    const float* W_t2   = (const float*)d_in[7];
    const float* b_t2   = (const float*)d_in[8];
    const float* W_node = (const float*)d_in[9];
    const float* b_node = (const float*)d_in[10];
    const float* Wm1    = (const float*)d_in[11];
    const float* bm1    = (const float*)d_in[12];
    const float* Wm2    = (const float*)d_in[13];
    const float* bm2    = (const float*)d_in[14];
    const float* Wn1    = (const float*)d_in[15];
    const float* bn1    = (const float*)d_in[16];
    const float* Wn2    = (const float*)d_in[17];
    const float* bn2    = (const float*)d_in[18];
    const float* Wc1    = (const float*)d_in[19];
    const float* bc1    = (const float*)d_in[20];
    const float* Wc2    = (const float*)d_in[21];
    const float* Wo1    = (const float*)d_in[22];
    const float* bo1    = (const float*)d_in[23];
    const float* Wo2    = (const float*)d_in[24];
    const float* bo2    = (const float*)d_in[25];
    float* out = (float*)d_out;

    float *p_h, *p_m1, *p_m, *p_n1, *p_cupd;
    int *p_deg;
    cudaGetSymbolAddress((void**)&p_h, g_h);
    cudaGetSymbolAddress((void**)&p_m1, g_m1);
    cudaGetSymbolAddress((void**)&p_m, g_m);
    cudaGetSymbolAddress((void**)&p_n1, g_n1);
    cudaGetSymbolAddress((void**)&p_cupd, g_cupd);
    cudaGetSymbolAddress((void**)&p_deg, g_deg);

    cudaFuncSetAttribute(gemm_tc<0, 0>, cudaFuncAttributeMaxDynamicSharedMemorySize, DSMEM_BYTES);
    cudaFuncSetAttribute(gemm_tc<0, 1>, cudaFuncAttributeMaxDynamicSharedMemorySize, DSMEM_BYTES);
    cudaFuncSetAttribute(gemm_tc<0, 2>, cudaFuncAttributeMaxDynamicSharedMemorySize, DSMEM_BYTES);
    cudaFuncSetAttribute(gemm_tc<1, 0>, cudaFuncAttributeMaxDynamicSharedMemorySize, DSMEM_BYTES);
    cudaFuncSetAttribute(gemm_tc<2, 0>, cudaFuncAttributeMaxDynamicSharedMemorySize, DSMEM_BYTES);

    // embeddings, init, CSR
    time_embed_k<<<1, 128>>>(t, W_t1, b_t1, W_t2, b_t2);
    table4_k<<<4, 128>>>(emb, W_node, b_node);
    h_init_k<<<cdiv((long)BB * NN * HH, 256), 256>>>(types);
    init_x_k<<<cdiv((long)BB * NN * 3, 256), 256>>>(x);
    zero_i_k<<<cdiv(NN, 256), 256>>>(p_deg, NN);
    deg_count_k<<<cdiv(EE, 256), 256>>>(bonds);
    scan_k<<<1, 256>>>();
    fill_k<<<cdiv(EE, 256), 256>>>(bonds);

    const int gridE = BB * EE / 128;  // 2500
    const int gridN = BB * NN / 128;  // 1250

    for (int l = 0; l < LL; l++) {
        zero_f_k<<<cdiv((long)BB * NN * 3, 256), 256>>>(p_cupd, (long)BB * NN * 3);
        edge_geom_k<<<cdiv((long)BB * EE, 256), 256>>>(bonds);

        // m1 = silu([h_src|h_dst] @ Wm1[0:256] + dist*Wm1[256] + bm1)
        gemm_tc<1, 0><<<gridE, 256, DSMEM_BYTES>>>(
            nullptr, Wm1 + (long)l * 257 * 128, bm1 + l * 128,
            Wm1 + ((long)l * 257 + 256) * 128, nullptr, p_m1, 256, bonds);
        // m = silu(m1 @ Wm2 + bm2)
        gemm_tc<0, 0><<<gridE, 256, DSMEM_BYTES>>>(
            p_m1, Wm2 + (long)l * 16384, bm2 + l * 128, nullptr, nullptr, p_m, 128, nullptr);
        // cw = silu(m @ Wc1 + bc1) . Wc2 ; coord atomics (fused)
        gemm_tc<0, 2><<<gridE, 256, DSMEM_BYTES>>>(
            p_m, Wc1 + (long)l * 16384, bc1 + l * 128, Wc2 + l * 128, nullptr, nullptr, 128, bonds);

        agg_gather_k<<<cdiv((long)BB * NN * 32, 256), 256>>>();

        // n1 = silu([h|agg] @ Wn1 + bn1)
        gemm_tc<2, 0><<<gridN, 256, DSMEM_BYTES>>>(
            nullptr, Wn1 + (long)l * 256 * 128, bn1 + l * 128, nullptr, nullptr, p_n1, 256, nullptr);
        // h = h + n1 @ Wn2 + bn2
        gemm_tc<0, 1><<<gridN, 256, DSMEM_BYTES>>>(
            p_n1, Wn2 + (long)l * 16384, bn2 + l * 128, nullptr, p_h, p_h, 128, nullptr);

        x_update_k<<<cdiv((long)BB * NN * 3, 256), 256>>>();
    }

    // o1 = silu(h @ W_o1 + b_o1) -> g_n1, then final combine
    gemm_tc<0, 0><<<gridN, 256, DSMEM_BYTES>>>(
        p_h, Wo1, bo1, nullptr, nullptr, p_n1, 128, nullptr);
    out_k<<<cdiv((long)BB * NN * 32, 256), 256>>>(Wo2, bo2, x, out);
}